// round 1
// baseline (speedup 1.0000x reference)
#include <cuda_runtime.h>
#include <cuda_bf16.h>
#include <math.h>
#include <float.h>

// Problem constants
#define BATCH 2
#define SEQ   2048
#define DMODEL 2048
#define NH    32
#define NKV   8
#define REP   4
#define HD    64
#define TOKENS (BATCH*SEQ)   // 4096
#define QDIM  (NH*HD)        // 2048
#define KVDIM (NKV*HD)       // 512

// Scratch (device globals: allocation-free)
__device__ float g_Q[TOKENS*QDIM];     // 32 MB
__device__ float g_K[TOKENS*KVDIM];    // 8 MB
__device__ float g_V[TOKENS*KVDIM];    // 8 MB
__device__ float g_A[TOKENS*QDIM];     // 32 MB
__device__ float g_cos[SEQ*(HD/2)];
__device__ float g_sin[SEQ*(HD/2)];

// ---------------------------------------------------------------------------
// RoPE tables. Reference computes in fp32; we compute the power and cos/sin in
// double and round to fp32 to be within ~1ulp of the reference regardless of
// --use_fast_math.
// ---------------------------------------------------------------------------
__global__ void rope_table_kernel() {
    int idx = blockIdx.x * blockDim.x + threadIdx.x;
    if (idx >= SEQ*(HD/2)) return;
    int pos = idx >> 5;        // /32
    int i   = idx & 31;
    double expo = (2.0 * i) / 64.0;
    float invf = (float)(1.0 / pow(10000.0, expo));
    float fr = (float)pos * invf;           // fp32 angle, matching reference
    double a = (double)fr;
    g_cos[idx] = (float)cos(a);
    g_sin[idx] = (float)sin(a);
}

// ---------------------------------------------------------------------------
// In-place RoPE on [TOKENS, nheads*64]
// ---------------------------------------------------------------------------
__global__ void rope_kernel(float* M, int nheads) {
    int idx = blockIdx.x * blockDim.x + threadIdx.x;
    int total = TOKENS * nheads * 32;
    if (idx >= total) return;
    int i  = idx & 31;
    int t2 = idx >> 5;
    int hh = t2 % nheads;
    int t  = t2 / nheads;
    int pos = t & (SEQ-1);
    float c = g_cos[pos*32 + i];
    float s = g_sin[pos*32 + i];
    float* p = M + (size_t)t * (nheads*64) + hh*64;
    float x1 = p[i];
    float x2 = p[i+32];
    p[i]    = x1*c - x2*s;
    p[i+32] = x1*s + x2*c;
}

// ---------------------------------------------------------------------------
// Generic fp32 GEMM: C[M,N] = A[M,K] * B[K,N], row-major.
// 64x64 tile, BK=16, 256 threads, 4x4 microtile, float4 smem reads.
// M,N multiples of 64; K multiple of 16.
// ---------------------------------------------------------------------------
__global__ __launch_bounds__(256) void gemm64(const float* __restrict__ A,
                                              const float* __restrict__ B,
                                              float* __restrict__ C,
                                              int M, int N, int K) {
    __shared__ float As[16][64];
    __shared__ float Bs[16][64];
    int bx = blockIdx.x, by = blockIdx.y;
    int tid = threadIdx.x;
    int tx = tid & 15, ty = tid >> 4;
    const float* Ablk = A + (size_t)by*64*K;
    const float* Bblk = B + bx*64;
    float acc[4][4] = {};
    for (int k0 = 0; k0 < K; k0 += 16) {
        #pragma unroll
        for (int i = 0; i < 4; i++) {
            int idx = tid + i*256;
            int m = idx >> 4, k = idx & 15;
            As[k][m] = Ablk[(size_t)m*K + k0 + k];
        }
        #pragma unroll
        for (int i = 0; i < 4; i++) {
            int idx = tid + i*256;
            int k = idx >> 6, n = idx & 63;
            Bs[k][n] = Bblk[(size_t)(k0+k)*N + n];
        }
        __syncthreads();
        #pragma unroll
        for (int k = 0; k < 16; k++) {
            float4 a = *(const float4*)&As[k][ty*4];
            float4 b = *(const float4*)&Bs[k][tx*4];
            acc[0][0] += a.x*b.x; acc[0][1] += a.x*b.y; acc[0][2] += a.x*b.z; acc[0][3] += a.x*b.w;
            acc[1][0] += a.y*b.x; acc[1][1] += a.y*b.y; acc[1][2] += a.y*b.z; acc[1][3] += a.y*b.w;
            acc[2][0] += a.z*b.x; acc[2][1] += a.z*b.y; acc[2][2] += a.z*b.z; acc[2][3] += a.z*b.w;
            acc[3][0] += a.w*b.x; acc[3][1] += a.w*b.y; acc[3][2] += a.w*b.z; acc[3][3] += a.w*b.w;
        }
        __syncthreads();
    }
    #pragma unroll
    for (int i = 0; i < 4; i++) {
        float4 v = make_float4(acc[i][0], acc[i][1], acc[i][2], acc[i][3]);
        *(float4*)&C[(size_t)(by*64 + ty*4 + i)*N + bx*64 + tx*4] = v;
    }
}

// ---------------------------------------------------------------------------
// Causal flash attention, fp32. One block per (q-tile of 64, b*H + h).
// BM=BN=64, HD=64. 256 threads, 4x4 fragments.
// Smem: Qs[d][m] (16KB) + Ks[d][n] (16KB, aliased as P[kcol][qrow]) + Vs[n][d]
// (16KB) = 48KB exactly.
// ---------------------------------------------------------------------------
__global__ __launch_bounds__(256) void flash_kernel(const float* __restrict__ Q,
                                                    const float* __restrict__ K,
                                                    const float* __restrict__ V,
                                                    float* __restrict__ O) {
    __shared__ float Qs[64][64];   // [d][qrow]
    __shared__ float Ks[64][64];   // [d][krow]; aliased as P[krow][qrow]
    __shared__ float Vs[64][64];   // [krow][d]

    int qt = blockIdx.x;                // q tile (0..31)
    int bh = blockIdx.y;                // b*32 + h
    int b = bh >> 5;
    int h = bh & 31;
    int g = h >> 2;                     // kv head = h / REP

    int tid = threadIdx.x;
    int tx = tid & 15, ty = tid >> 4;

    const float* Qbase = Q + (size_t)b*SEQ*QDIM + h*64;
    const float* Kbase = K + (size_t)b*SEQ*KVDIM + g*64;
    const float* Vbase = V + (size_t)b*SEQ*KVDIM + g*64;

    // Load Q tile (transposed into smem)
    for (int idx = tid; idx < 4096; idx += 256) {
        int m = idx >> 6, d = idx & 63;
        Qs[d][m] = Qbase[(size_t)(qt*64 + m)*QDIM + d];
    }
    __syncthreads();

    float m_i[4], l_i[4], o[4][4];
    #pragma unroll
    for (int i = 0; i < 4; i++) { m_i[i] = -FLT_MAX; l_i[i] = 0.f; }
    #pragma unroll
    for (int i = 0; i < 4; i++)
        #pragma unroll
        for (int j = 0; j < 4; j++) o[i][j] = 0.f;

    const float scale = 0.125f; // 1/sqrt(64)

    for (int kt = 0; kt <= qt; kt++) {
        // load K (transposed) and V tiles
        for (int idx = tid; idx < 4096; idx += 256) {
            int r = idx >> 6, d = idx & 63;
            Ks[d][r] = Kbase[(size_t)(kt*64 + r)*KVDIM + d];
            Vs[r][d] = Vbase[(size_t)(kt*64 + r)*KVDIM + d];
        }
        __syncthreads();

        // S = Q * K^T (fragment)
        float s[4][4] = {};
        #pragma unroll 8
        for (int d = 0; d < 64; d++) {
            float4 a = *(const float4*)&Qs[d][ty*4];
            float4 bb = *(const float4*)&Ks[d][tx*4];
            s[0][0] += a.x*bb.x; s[0][1] += a.x*bb.y; s[0][2] += a.x*bb.z; s[0][3] += a.x*bb.w;
            s[1][0] += a.y*bb.x; s[1][1] += a.y*bb.y; s[1][2] += a.y*bb.z; s[1][3] += a.y*bb.w;
            s[2][0] += a.z*bb.x; s[2][1] += a.z*bb.y; s[2][2] += a.z*bb.z; s[2][3] += a.z*bb.w;
            s[3][0] += a.w*bb.x; s[3][1] += a.w*bb.y; s[3][2] += a.w*bb.z; s[3][3] += a.w*bb.w;
        }
        // scale + causal mask (only the diagonal tile needs masking)
        if (kt == qt) {
            #pragma unroll
            for (int i = 0; i < 4; i++) {
                int qpos = ty*4 + i;
                #pragma unroll
                for (int j = 0; j < 4; j++) {
                    int kpos = tx*4 + j;
                    s[i][j] = (kpos > qpos) ? -FLT_MAX : s[i][j]*scale;
                }
            }
        } else {
            #pragma unroll
            for (int i = 0; i < 4; i++)
                #pragma unroll
                for (int j = 0; j < 4; j++) s[i][j] *= scale;
        }

        // online softmax update
        float fac[4], rsum[4];
        #pragma unroll
        for (int i = 0; i < 4; i++) {
            float mt = fmaxf(fmaxf(s[i][0], s[i][1]), fmaxf(s[i][2], s[i][3]));
            #pragma unroll
            for (int off = 8; off >= 1; off >>= 1)
                mt = fmaxf(mt, __shfl_xor_sync(0xffffffffu, mt, off));
            float mn = fmaxf(m_i[i], mt);
            fac[i] = expf(m_i[i] - mn);
            m_i[i] = mn;
            float rs = 0.f;
            #pragma unroll
            for (int j = 0; j < 4; j++) {
                s[i][j] = expf(s[i][j] - mn);
                rs += s[i][j];
            }
            #pragma unroll
            for (int off = 8; off >= 1; off >>= 1)
                rs += __shfl_xor_sync(0xffffffffu, rs, off);
            rsum[i] = rs;
        }
        #pragma unroll
        for (int i = 0; i < 4; i++) {
            l_i[i] = l_i[i]*fac[i] + rsum[i];
            #pragma unroll
            for (int j = 0; j < 4; j++) o[i][j] *= fac[i];
        }

        // write P (transposed: P[kcol][qrow]) into Ks' smem
        __syncthreads();
        float* Ps = &Ks[0][0];
        #pragma unroll
        for (int j = 0; j < 4; j++) {
            float4 v = make_float4(s[0][j], s[1][j], s[2][j], s[3][j]);
            *(float4*)&Ps[(tx*4 + j)*64 + ty*4] = v;
        }
        __syncthreads();

        // O += P * V
        #pragma unroll 8
        for (int kk = 0; kk < 64; kk++) {
            float4 p4 = *(const float4*)&Ps[kk*64 + ty*4];
            float4 v4 = *(const float4*)&Vs[kk][tx*4];
            o[0][0] += p4.x*v4.x; o[0][1] += p4.x*v4.y; o[0][2] += p4.x*v4.z; o[0][3] += p4.x*v4.w;
            o[1][0] += p4.y*v4.x; o[1][1] += p4.y*v4.y; o[1][2] += p4.y*v4.z; o[1][3] += p4.y*v4.w;
            o[2][0] += p4.z*v4.x; o[2][1] += p4.z*v4.y; o[2][2] += p4.z*v4.z; o[2][3] += p4.z*v4.w;
            o[3][0] += p4.w*v4.x; o[3][1] += p4.w*v4.y; o[3][2] += p4.w*v4.z; o[3][3] += p4.w*v4.w;
        }
        __syncthreads();
    }

    // finalize and write
    #pragma unroll
    for (int i = 0; i < 4; i++) {
        float inv = 1.0f / l_i[i];
        float4 v = make_float4(o[i][0]*inv, o[i][1]*inv, o[i][2]*inv, o[i][3]*inv);
        size_t row = (size_t)b*SEQ + qt*64 + ty*4 + i;
        *(float4*)&g_A[row*QDIM + h*64 + tx*4] = v;
    }
}

// ---------------------------------------------------------------------------
extern "C" void kernel_launch(void* const* d_in, const int* in_sizes, int n_in,
                              void* d_out, int out_size) {
    (void)in_sizes; (void)n_in; (void)out_size;
    const float* x  = (const float*)d_in[0];
    const float* wq = (const float*)d_in[1];
    const float* wk = (const float*)d_in[2];
    const float* wv = (const float*)d_in[3];
    const float* wo = (const float*)d_in[4];
    float* out = (float*)d_out;

    float *Qp, *Kp, *Vp, *Ap;
    cudaGetSymbolAddress((void**)&Qp, g_Q);
    cudaGetSymbolAddress((void**)&Kp, g_K);
    cudaGetSymbolAddress((void**)&Vp, g_V);
    cudaGetSymbolAddress((void**)&Ap, g_A);

    // RoPE tables
    rope_table_kernel<<<(SEQ*32 + 255)/256, 256>>>();

    // Projections
    gemm64<<<dim3(QDIM/64,  TOKENS/64), 256>>>(x, wq, Qp, TOKENS, QDIM,  DMODEL);
    gemm64<<<dim3(KVDIM/64, TOKENS/64), 256>>>(x, wk, Kp, TOKENS, KVDIM, DMODEL);
    gemm64<<<dim3(KVDIM/64, TOKENS/64), 256>>>(x, wv, Vp, TOKENS, KVDIM, DMODEL);

    // RoPE
    rope_kernel<<<(TOKENS*NH*32 + 255)/256, 256>>>(Qp, NH);
    rope_kernel<<<(TOKENS*NKV*32 + 255)/256, 256>>>(Kp, NKV);

    // Flash attention
    flash_kernel<<<dim3(SEQ/64, BATCH*NH), 256>>>(Qp, Kp, Vp, Ap);

    // Output projection
    gemm64<<<dim3(DMODEL/64, TOKENS/64), 256>>>(Ap, wo, out, TOKENS, DMODEL, QDIM);
}

// round 4
// speedup vs baseline: 1.7733x; 1.7733x over previous
#include <cuda_runtime.h>
#include <cuda_bf16.h>
#include <math.h>
#include <float.h>
#include <stdint.h>

// Problem constants
#define BATCH 2
#define SEQ   2048
#define DMODEL 2048
#define NH    32
#define NKV   8
#define REP   4
#define HD    64
#define TOKENS (BATCH*SEQ)   // 4096
#define QDIM  (NH*HD)        // 2048
#define KVDIM (NKV*HD)       // 512

// Scratch (device globals: allocation-free)
__device__ float g_Q[TOKENS*QDIM];     // 32 MB
__device__ float g_K[TOKENS*KVDIM];    // 8 MB
__device__ float g_V[TOKENS*KVDIM];    // 8 MB
__device__ float g_A[TOKENS*QDIM];     // 32 MB
__device__ float g_cos[SEQ*(HD/2)];
__device__ float g_sin[SEQ*(HD/2)];

// ---------------------------------------------------------------------------
// RoPE tables (double precision internally; fp32 angle matches reference)
// ---------------------------------------------------------------------------
__global__ void rope_table_kernel() {
    int idx = blockIdx.x * blockDim.x + threadIdx.x;
    if (idx >= SEQ*(HD/2)) return;
    int pos = idx >> 5;
    int i   = idx & 31;
    double expo = (2.0 * i) / 64.0;
    float invf = (float)(1.0 / pow(10000.0, expo));
    float fr = (float)pos * invf;
    double a = (double)fr;
    g_cos[idx] = (float)cos(a);
    g_sin[idx] = (float)sin(a);
}

// ---------------------------------------------------------------------------
// In-place RoPE on [TOKENS, nheads*64]
// ---------------------------------------------------------------------------
__global__ void rope_kernel(float* M, int nheads) {
    int idx = blockIdx.x * blockDim.x + threadIdx.x;
    int total = TOKENS * nheads * 32;
    if (idx >= total) return;
    int i  = idx & 31;
    int t2 = idx >> 5;
    int hh = t2 % nheads;
    int t  = t2 / nheads;
    int pos = t & (SEQ-1);
    float c = g_cos[pos*32 + i];
    float s = g_sin[pos*32 + i];
    float* p = M + (size_t)t * (nheads*64) + hh*64;
    float x1 = p[i];
    float x2 = p[i+32];
    p[i]    = x1*c - x2*s;
    p[i+32] = x1*s + x2*c;
}

// ---------------------------------------------------------------------------
// tf32 tensor-core GEMM: C[M,N] = A[M,K]*B[K,N], row-major.
// Block tile 128x128, BK=16, 256 threads = 8 warps in 4(M) x 2(N).
// Warp tile 32x64 = 2x8 m16n8k8 mma fragments.
// Smem rows padded to 136 floats -> all fragment LDS conflict-free.
// ---------------------------------------------------------------------------
#define BM 128
#define BN 128
#define BKG 16
#define SPAD 136

__device__ __forceinline__ uint32_t f2tf32(float x) {
    uint32_t r;
    asm("cvt.rna.tf32.f32 %0, %1;" : "=r"(r) : "f"(x));
    return r;
}

__global__ __launch_bounds__(256) void gemm_tf32(const float* __restrict__ A,
                                                 const float* __restrict__ B,
                                                 float* __restrict__ C,
                                                 int M, int N, int K) {
    __shared__ float As[BKG][SPAD];   // [k][m]
    __shared__ float Bs[BKG][SPAD];   // [k][n]

    int tid  = threadIdx.x;
    int lane = tid & 31, warp = tid >> 5;
    int wm = warp & 3, wn = warp >> 2;       // 4 x 2 warp grid
    int m_warp = wm * 32, n_warp = wn * 64;
    int g  = lane >> 2;                      // groupID 0..7
    int tg = lane & 3;                       // thread-in-group 0..3

    const float* Ablk = A + (size_t)blockIdx.y * BM * K;
    const float* Bblk = B + (size_t)blockIdx.x * BN;

    float acc[2][8][4];
    #pragma unroll
    for (int mi = 0; mi < 2; mi++)
        #pragma unroll
        for (int ni = 0; ni < 8; ni++)
            #pragma unroll
            for (int c = 0; c < 4; c++) acc[mi][ni][c] = 0.f;

    // global->smem load assignments
    int am = tid >> 1, ak = (tid & 1) * 8;   // A: 128 rows x 16 k
    int bk = tid >> 4, bn = (tid & 15) * 8;  // B: 16 k-rows x 128 n

    for (int k0 = 0; k0 < K; k0 += BKG) {
        float4 av0 = *(const float4*)&Ablk[(size_t)am*K + k0 + ak];
        float4 av1 = *(const float4*)&Ablk[(size_t)am*K + k0 + ak + 4];
        As[ak+0][am] = av0.x; As[ak+1][am] = av0.y;
        As[ak+2][am] = av0.z; As[ak+3][am] = av0.w;
        As[ak+4][am] = av1.x; As[ak+5][am] = av1.y;
        As[ak+6][am] = av1.z; As[ak+7][am] = av1.w;

        float4 bv0 = *(const float4*)&Bblk[(size_t)(k0+bk)*N + bn];
        float4 bv1 = *(const float4*)&Bblk[(size_t)(k0+bk)*N + bn + 4];
        *(float4*)&Bs[bk][bn]     = bv0;
        *(float4*)&Bs[bk][bn + 4] = bv1;
        __syncthreads();

        #pragma unroll
        for (int kk = 0; kk < BKG; kk += 8) {
            uint32_t afr[2][4];
            #pragma unroll
            for (int mi = 0; mi < 2; mi++) {
                int mb = m_warp + mi*16;
                afr[mi][0] = f2tf32(As[kk+tg  ][mb + g    ]);
                afr[mi][1] = f2tf32(As[kk+tg  ][mb + g + 8]);
                afr[mi][2] = f2tf32(As[kk+tg+4][mb + g    ]);
                afr[mi][3] = f2tf32(As[kk+tg+4][mb + g + 8]);
            }
            uint32_t bfr[8][2];
            #pragma unroll
            for (int ni = 0; ni < 8; ni++) {
                int nb = n_warp + ni*8;
                bfr[ni][0] = f2tf32(Bs[kk+tg  ][nb + g]);
                bfr[ni][1] = f2tf32(Bs[kk+tg+4][nb + g]);
            }
            #pragma unroll
            for (int mi = 0; mi < 2; mi++)
                #pragma unroll
                for (int ni = 0; ni < 8; ni++) {
                    asm volatile(
                        "mma.sync.aligned.m16n8k8.row.col.f32.tf32.tf32.f32 "
                        "{%0,%1,%2,%3}, {%4,%5,%6,%7}, {%8,%9}, {%0,%1,%2,%3};"
                        : "+f"(acc[mi][ni][0]), "+f"(acc[mi][ni][1]),
                          "+f"(acc[mi][ni][2]), "+f"(acc[mi][ni][3])
                        : "r"(afr[mi][0]), "r"(afr[mi][1]),
                          "r"(afr[mi][2]), "r"(afr[mi][3]),
                          "r"(bfr[ni][0]), "r"(bfr[ni][1]));
                }
        }
        __syncthreads();
    }

    // epilogue
    size_t rowbase = (size_t)blockIdx.y * BM + m_warp + g;
    int colbase = blockIdx.x * BN + n_warp + tg*2;
    #pragma unroll
    for (int mi = 0; mi < 2; mi++) {
        size_t r0 = rowbase + mi*16;
        #pragma unroll
        for (int ni = 0; ni < 8; ni++) {
            int c = colbase + ni*8;
            *(float2*)&C[r0*N + c]       = make_float2(acc[mi][ni][0], acc[mi][ni][1]);
            *(float2*)&C[(r0+8)*N + c]   = make_float2(acc[mi][ni][2], acc[mi][ni][3]);
        }
    }
}

// ---------------------------------------------------------------------------
// Causal flash attention, fp32 (unchanged this round).
// ---------------------------------------------------------------------------
__global__ __launch_bounds__(256) void flash_kernel(const float* __restrict__ Q,
                                                    const float* __restrict__ K,
                                                    const float* __restrict__ V,
                                                    float* __restrict__ O) {
    __shared__ float Qs[64][64];
    __shared__ float Ks[64][64];
    __shared__ float Vs[64][64];

    int qt = blockIdx.x;
    int bh = blockIdx.y;
    int b = bh >> 5;
    int h = bh & 31;
    int g = h >> 2;

    int tid = threadIdx.x;
    int tx = tid & 15, ty = tid >> 4;

    const float* Qbase = Q + (size_t)b*SEQ*QDIM + h*64;
    const float* Kbase = K + (size_t)b*SEQ*KVDIM + g*64;
    const float* Vbase = V + (size_t)b*SEQ*KVDIM + g*64;

    for (int idx = tid; idx < 4096; idx += 256) {
        int m = idx >> 6, d = idx & 63;
        Qs[d][m] = Qbase[(size_t)(qt*64 + m)*QDIM + d];
    }
    __syncthreads();

    float m_i[4], l_i[4], o[4][4];
    #pragma unroll
    for (int i = 0; i < 4; i++) { m_i[i] = -FLT_MAX; l_i[i] = 0.f; }
    #pragma unroll
    for (int i = 0; i < 4; i++)
        #pragma unroll
        for (int j = 0; j < 4; j++) o[i][j] = 0.f;

    const float scale = 0.125f;

    for (int kt = 0; kt <= qt; kt++) {
        for (int idx = tid; idx < 4096; idx += 256) {
            int r = idx >> 6, d = idx & 63;
            Ks[d][r] = Kbase[(size_t)(kt*64 + r)*KVDIM + d];
            Vs[r][d] = Vbase[(size_t)(kt*64 + r)*KVDIM + d];
        }
        __syncthreads();

        float s[4][4] = {};
        #pragma unroll 8
        for (int d = 0; d < 64; d++) {
            float4 a = *(const float4*)&Qs[d][ty*4];
            float4 bb = *(const float4*)&Ks[d][tx*4];
            s[0][0] += a.x*bb.x; s[0][1] += a.x*bb.y; s[0][2] += a.x*bb.z; s[0][3] += a.x*bb.w;
            s[1][0] += a.y*bb.x; s[1][1] += a.y*bb.y; s[1][2] += a.y*bb.z; s[1][3] += a.y*bb.w;
            s[2][0] += a.z*bb.x; s[2][1] += a.z*bb.y; s[2][2] += a.z*bb.z; s[2][3] += a.z*bb.w;
            s[3][0] += a.w*bb.x; s[3][1] += a.w*bb.y; s[3][2] += a.w*bb.z; s[3][3] += a.w*bb.w;
        }
        if (kt == qt) {
            #pragma unroll
            for (int i = 0; i < 4; i++) {
                int qpos = ty*4 + i;
                #pragma unroll
                for (int j = 0; j < 4; j++) {
                    int kpos = tx*4 + j;
                    s[i][j] = (kpos > qpos) ? -FLT_MAX : s[i][j]*scale;
                }
            }
        } else {
            #pragma unroll
            for (int i = 0; i < 4; i++)
                #pragma unroll
                for (int j = 0; j < 4; j++) s[i][j] *= scale;
        }

        float fac[4], rsum[4];
        #pragma unroll
        for (int i = 0; i < 4; i++) {
            float mt = fmaxf(fmaxf(s[i][0], s[i][1]), fmaxf(s[i][2], s[i][3]));
            #pragma unroll
            for (int off = 8; off >= 1; off >>= 1)
                mt = fmaxf(mt, __shfl_xor_sync(0xffffffffu, mt, off));
            float mn = fmaxf(m_i[i], mt);
            fac[i] = expf(m_i[i] - mn);
            m_i[i] = mn;
            float rs = 0.f;
            #pragma unroll
            for (int j = 0; j < 4; j++) {
                s[i][j] = expf(s[i][j] - mn);
                rs += s[i][j];
            }
            #pragma unroll
            for (int off = 8; off >= 1; off >>= 1)
                rs += __shfl_xor_sync(0xffffffffu, rs, off);
            rsum[i] = rs;
        }
        #pragma unroll
        for (int i = 0; i < 4; i++) {
            l_i[i] = l_i[i]*fac[i] + rsum[i];
            #pragma unroll
            for (int j = 0; j < 4; j++) o[i][j] *= fac[i];
        }

        __syncthreads();
        float* Ps = &Ks[0][0];
        #pragma unroll
        for (int j = 0; j < 4; j++) {
            float4 v = make_float4(s[0][j], s[1][j], s[2][j], s[3][j]);
            *(float4*)&Ps[(tx*4 + j)*64 + ty*4] = v;
        }
        __syncthreads();

        #pragma unroll 8
        for (int kk = 0; kk < 64; kk++) {
            float4 p4 = *(const float4*)&Ps[kk*64 + ty*4];
            float4 v4 = *(const float4*)&Vs[kk][tx*4];
            o[0][0] += p4.x*v4.x; o[0][1] += p4.x*v4.y; o[0][2] += p4.x*v4.z; o[0][3] += p4.x*v4.w;
            o[1][0] += p4.y*v4.x; o[1][1] += p4.y*v4.y; o[1][2] += p4.y*v4.z; o[1][3] += p4.y*v4.w;
            o[2][0] += p4.z*v4.x; o[2][1] += p4.z*v4.y; o[2][2] += p4.z*v4.z; o[2][3] += p4.z*v4.w;
            o[3][0] += p4.w*v4.x; o[3][1] += p4.w*v4.y; o[3][2] += p4.w*v4.z; o[3][3] += p4.w*v4.w;
        }
        __syncthreads();
    }

    #pragma unroll
    for (int i = 0; i < 4; i++) {
        float inv = 1.0f / l_i[i];
        float4 v = make_float4(o[i][0]*inv, o[i][1]*inv, o[i][2]*inv, o[i][3]*inv);
        size_t row = (size_t)b*SEQ + qt*64 + ty*4 + i;
        *(float4*)&g_A[row*QDIM + h*64 + tx*4] = v;
    }
}

// ---------------------------------------------------------------------------
extern "C" void kernel_launch(void* const* d_in, const int* in_sizes, int n_in,
                              void* d_out, int out_size) {
    (void)in_sizes; (void)n_in; (void)out_size;
    const float* x  = (const float*)d_in[0];
    const float* wq = (const float*)d_in[1];
    const float* wk = (const float*)d_in[2];
    const float* wv = (const float*)d_in[3];
    const float* wo = (const float*)d_in[4];
    float* out = (float*)d_out;

    float *Qp, *Kp, *Vp, *Ap;
    cudaGetSymbolAddress((void**)&Qp, g_Q);
    cudaGetSymbolAddress((void**)&Kp, g_K);
    cudaGetSymbolAddress((void**)&Vp, g_V);
    cudaGetSymbolAddress((void**)&Ap, g_A);

    rope_table_kernel<<<(SEQ*32 + 255)/256, 256>>>();

    gemm_tf32<<<dim3(QDIM/BN,  TOKENS/BM), 256>>>(x, wq, Qp, TOKENS, QDIM,  DMODEL);
    gemm_tf32<<<dim3(KVDIM/BN, TOKENS/BM), 256>>>(x, wk, Kp, TOKENS, KVDIM, DMODEL);
    gemm_tf32<<<dim3(KVDIM/BN, TOKENS/BM), 256>>>(x, wv, Vp, TOKENS, KVDIM, DMODEL);

    rope_kernel<<<(TOKENS*NH*32 + 255)/256, 256>>>(Qp, NH);
    rope_kernel<<<(TOKENS*NKV*32 + 255)/256, 256>>>(Kp, NKV);

    flash_kernel<<<dim3(SEQ/64, BATCH*NH), 256>>>(Qp, Kp, Vp, Ap);

    gemm_tf32<<<dim3(DMODEL/BN, TOKENS/BM), 256>>>(Ap, wo, out, TOKENS, DMODEL, QDIM);
}

// round 5
// speedup vs baseline: 2.3291x; 1.3134x over previous
#include <cuda_runtime.h>
#include <cuda_bf16.h>
#include <math.h>
#include <float.h>
#include <stdint.h>

// Problem constants
#define BATCH 2
#define SEQ   2048
#define DMODEL 2048
#define NH    32
#define NKV   8
#define REP   4
#define HD    64
#define TOKENS (BATCH*SEQ)   // 4096
#define QDIM  (NH*HD)        // 2048
#define KVDIM (NKV*HD)       // 512

// Scratch (device globals: allocation-free)
__device__ float g_Q[TOKENS*QDIM];     // 32 MB
__device__ float g_K[TOKENS*KVDIM];    // 8 MB
__device__ float g_V[TOKENS*KVDIM];    // 8 MB
__device__ float g_A[TOKENS*QDIM];     // 32 MB
__device__ float g_cos[SEQ*(HD/2)];
__device__ float g_sin[SEQ*(HD/2)];

__device__ __forceinline__ uint32_t f2tf32(float x) {
    uint32_t r;
    asm("cvt.rna.tf32.f32 %0, %1;" : "=r"(r) : "f"(x));
    return r;
}
__device__ __forceinline__ float tf32f(float x) {
    return __uint_as_float(f2tf32(x));
}
__device__ __forceinline__ void mma_tf32(float* c, const uint32_t* a, uint32_t b0, uint32_t b1) {
    asm volatile("mma.sync.aligned.m16n8k8.row.col.f32.tf32.tf32.f32 "
                 "{%0,%1,%2,%3}, {%4,%5,%6,%7}, {%8,%9}, {%0,%1,%2,%3};"
                 : "+f"(c[0]), "+f"(c[1]), "+f"(c[2]), "+f"(c[3])
                 : "r"(a[0]), "r"(a[1]), "r"(a[2]), "r"(a[3]), "r"(b0), "r"(b1));
}

// ---------------------------------------------------------------------------
// RoPE tables (double precision internally; fp32 angle matches reference)
// ---------------------------------------------------------------------------
__global__ void rope_table_kernel() {
    int idx = blockIdx.x * blockDim.x + threadIdx.x;
    if (idx >= SEQ*(HD/2)) return;
    int pos = idx >> 5;
    int i   = idx & 31;
    double expo = (2.0 * i) / 64.0;
    float invf = (float)(1.0 / pow(10000.0, expo));
    float fr = (float)pos * invf;
    double a = (double)fr;
    g_cos[idx] = (float)cos(a);
    g_sin[idx] = (float)sin(a);
}

// ---------------------------------------------------------------------------
// In-place RoPE on [TOKENS, nheads*64]
// ---------------------------------------------------------------------------
__global__ void rope_kernel(float* M, int nheads) {
    int idx = blockIdx.x * blockDim.x + threadIdx.x;
    int total = TOKENS * nheads * 32;
    if (idx >= total) return;
    int i  = idx & 31;
    int t2 = idx >> 5;
    int hh = t2 % nheads;
    int t  = t2 / nheads;
    int pos = t & (SEQ-1);
    float c = g_cos[pos*32 + i];
    float s = g_sin[pos*32 + i];
    float* p = M + (size_t)t * (nheads*64) + hh*64;
    float x1 = p[i];
    float x2 = p[i+32];
    p[i]    = x1*c - x2*s;
    p[i+32] = x1*s + x2*c;
}

// ---------------------------------------------------------------------------
// tf32 tensor-core GEMM (unchanged from R4): C[M,N] = A[M,K]*B[K,N]
// ---------------------------------------------------------------------------
#define BM 128
#define BN 128
#define BKG 16
#define SPAD 136

__global__ __launch_bounds__(256) void gemm_tf32(const float* __restrict__ A,
                                                 const float* __restrict__ B,
                                                 float* __restrict__ C,
                                                 int M, int N, int K) {
    __shared__ float As[BKG][SPAD];   // [k][m]
    __shared__ float Bs[BKG][SPAD];   // [k][n]

    int tid  = threadIdx.x;
    int lane = tid & 31, warp = tid >> 5;
    int wm = warp & 3, wn = warp >> 2;
    int m_warp = wm * 32, n_warp = wn * 64;
    int g  = lane >> 2;
    int tg = lane & 3;

    const float* Ablk = A + (size_t)blockIdx.y * BM * K;
    const float* Bblk = B + (size_t)blockIdx.x * BN;

    float acc[2][8][4];
    #pragma unroll
    for (int mi = 0; mi < 2; mi++)
        #pragma unroll
        for (int ni = 0; ni < 8; ni++)
            #pragma unroll
            for (int c = 0; c < 4; c++) acc[mi][ni][c] = 0.f;

    int am = tid >> 1, ak = (tid & 1) * 8;
    int bk = tid >> 4, bn = (tid & 15) * 8;

    for (int k0 = 0; k0 < K; k0 += BKG) {
        float4 av0 = *(const float4*)&Ablk[(size_t)am*K + k0 + ak];
        float4 av1 = *(const float4*)&Ablk[(size_t)am*K + k0 + ak + 4];
        As[ak+0][am] = av0.x; As[ak+1][am] = av0.y;
        As[ak+2][am] = av0.z; As[ak+3][am] = av0.w;
        As[ak+4][am] = av1.x; As[ak+5][am] = av1.y;
        As[ak+6][am] = av1.z; As[ak+7][am] = av1.w;

        float4 bv0 = *(const float4*)&Bblk[(size_t)(k0+bk)*N + bn];
        float4 bv1 = *(const float4*)&Bblk[(size_t)(k0+bk)*N + bn + 4];
        *(float4*)&Bs[bk][bn]     = bv0;
        *(float4*)&Bs[bk][bn + 4] = bv1;
        __syncthreads();

        #pragma unroll
        for (int kk = 0; kk < BKG; kk += 8) {
            uint32_t afr[2][4];
            #pragma unroll
            for (int mi = 0; mi < 2; mi++) {
                int mb = m_warp + mi*16;
                afr[mi][0] = f2tf32(As[kk+tg  ][mb + g    ]);
                afr[mi][1] = f2tf32(As[kk+tg  ][mb + g + 8]);
                afr[mi][2] = f2tf32(As[kk+tg+4][mb + g    ]);
                afr[mi][3] = f2tf32(As[kk+tg+4][mb + g + 8]);
            }
            uint32_t bfr[8][2];
            #pragma unroll
            for (int ni = 0; ni < 8; ni++) {
                int nb = n_warp + ni*8;
                bfr[ni][0] = f2tf32(Bs[kk+tg  ][nb + g]);
                bfr[ni][1] = f2tf32(Bs[kk+tg+4][nb + g]);
            }
            #pragma unroll
            for (int mi = 0; mi < 2; mi++)
                #pragma unroll
                for (int ni = 0; ni < 8; ni++)
                    mma_tf32(acc[mi][ni], afr[mi], bfr[ni][0], bfr[ni][1]);
        }
        __syncthreads();
    }

    size_t rowbase = (size_t)blockIdx.y * BM + m_warp + g;
    int colbase = blockIdx.x * BN + n_warp + tg*2;
    #pragma unroll
    for (int mi = 0; mi < 2; mi++) {
        size_t r0 = rowbase + mi*16;
        #pragma unroll
        for (int ni = 0; ni < 8; ni++) {
            int c = colbase + ni*8;
            *(float2*)&C[r0*N + c]     = make_float2(acc[mi][ni][0], acc[mi][ni][1]);
            *(float2*)&C[(r0+8)*N + c] = make_float2(acc[mi][ni][2], acc[mi][ni][3]);
        }
    }
}

// ---------------------------------------------------------------------------
// Tensor-core causal flash attention, 3xTF32 (near-fp32 accuracy).
// Block: 128 threads = 4 warps; warp w owns q-rows [w*16, w*16+16), all 64 cols.
// Tiles 64(q) x 64(k), HD=64. K/V pre-split into tf32 hi/lo smem per tile.
// Smem layouts (floats): Qs[m][d] pad 68, Kh/Kl[n][d] pad 68 (Kh aliased by P),
// Vh/Vl[k][d] pad 72. All mma fragment LDS patterns bank-conflict-free.
// ---------------------------------------------------------------------------
#define FPAD 68
#define VPAD 72
#define FLASH_SMEM ((3*64*FPAD + 2*64*VPAD)*4)   // 89088 bytes

__global__ __launch_bounds__(128) void flash_tc(const float* __restrict__ Q,
                                                const float* __restrict__ K,
                                                const float* __restrict__ V,
                                                float* __restrict__ O) {
    extern __shared__ float sm[];
    float* Qs = sm;                    // 64*68
    float* Kh = Qs + 64*FPAD;          // 64*68  (aliased as Ps)
    float* Kl = Kh + 64*FPAD;          // 64*68
    float* Vh = Kl + 64*FPAD;          // 64*72
    float* Vl = Vh + 64*VPAD;          // 64*72
    float* Ps = Kh;

    int qt = blockIdx.x;
    int bh = blockIdx.y;
    int b = bh >> 5, h = bh & 31, gkv = h >> 2;
    int tid = threadIdx.x;
    int lane = tid & 31, warp = tid >> 5;
    int g = lane >> 2, tg = lane & 3;
    int m0 = warp * 16;

    const float* Qbase = Q + (size_t)b*SEQ*QDIM + (size_t)(qt*64)*QDIM + h*64;
    const float* Kbase = K + (size_t)b*SEQ*KVDIM + gkv*64;
    const float* Vbase = V + (size_t)b*SEQ*KVDIM + gkv*64;

    // Load Q tile (warp-local rows: threads 2r,2r+1 of warp w write rows the
    // same warp later reads as A fragments)
    {
        int r = tid >> 1, c0 = (tid & 1) * 32;
        const float* src = Qbase + (size_t)r*QDIM + c0;
        float* dst = Qs + r*FPAD + c0;
        #pragma unroll
        for (int i = 0; i < 8; i++)
            *(float4*)(dst + i*4) = *(const float4*)(src + i*4);
    }

    float m_i[2] = {-FLT_MAX, -FLT_MAX};
    float l_i[2] = {0.f, 0.f};
    float o[8][4];
    #pragma unroll
    for (int nf = 0; nf < 8; nf++)
        #pragma unroll
        for (int c = 0; c < 4; c++) o[nf][c] = 0.f;

    const float scale = 0.125f;

    for (int kt = 0; kt <= qt; kt++) {
        __syncthreads();   // prior iteration done with Kh(P)/Vh/Vl (and Q load visible)
        // Load K,V tile; split into tf32 hi/lo
        {
            int r = tid >> 1, c0 = (tid & 1) * 32;
            const float* ksrc = Kbase + (size_t)(kt*64 + r)*KVDIM + c0;
            const float* vsrc = Vbase + (size_t)(kt*64 + r)*KVDIM + c0;
            float* khd = Kh + r*FPAD + c0;
            float* kld = Kl + r*FPAD + c0;
            float* vhd = Vh + r*VPAD + c0;
            float* vld = Vl + r*VPAD + c0;
            #pragma unroll
            for (int i = 0; i < 8; i++) {
                float4 kv = *(const float4*)(ksrc + i*4);
                float4 vv = *(const float4*)(vsrc + i*4);
                float4 kh4, kl4, vh4, vl4;
                kh4.x = tf32f(kv.x); kl4.x = tf32f(kv.x - kh4.x);
                kh4.y = tf32f(kv.y); kl4.y = tf32f(kv.y - kh4.y);
                kh4.z = tf32f(kv.z); kl4.z = tf32f(kv.z - kh4.z);
                kh4.w = tf32f(kv.w); kl4.w = tf32f(kv.w - kh4.w);
                vh4.x = tf32f(vv.x); vl4.x = tf32f(vv.x - vh4.x);
                vh4.y = tf32f(vv.y); vl4.y = tf32f(vv.y - vh4.y);
                vh4.z = tf32f(vv.z); vl4.z = tf32f(vv.z - vh4.z);
                vh4.w = tf32f(vv.w); vl4.w = tf32f(vv.w - vh4.w);
                *(float4*)(khd + i*4) = kh4;
                *(float4*)(kld + i*4) = kl4;
                *(float4*)(vhd + i*4) = vh4;
                *(float4*)(vld + i*4) = vl4;
            }
        }
        __syncthreads();

        // ---- S = Q * K^T (3xTF32) ----
        float s[8][4];
        #pragma unroll
        for (int nf = 0; nf < 8; nf++)
            #pragma unroll
            for (int c = 0; c < 4; c++) s[nf][c] = 0.f;

        #pragma unroll 2
        for (int kk = 0; kk < 64; kk += 8) {
            float a0 = Qs[(m0+g)*FPAD   + kk+tg];
            float a1 = Qs[(m0+g+8)*FPAD + kk+tg];
            float a2 = Qs[(m0+g)*FPAD   + kk+tg+4];
            float a3 = Qs[(m0+g+8)*FPAD + kk+tg+4];
            uint32_t ah[4], al[4];
            ah[0] = f2tf32(a0); al[0] = f2tf32(a0 - __uint_as_float(ah[0]));
            ah[1] = f2tf32(a1); al[1] = f2tf32(a1 - __uint_as_float(ah[1]));
            ah[2] = f2tf32(a2); al[2] = f2tf32(a2 - __uint_as_float(ah[2]));
            ah[3] = f2tf32(a3); al[3] = f2tf32(a3 - __uint_as_float(ah[3]));
            #pragma unroll
            for (int nf = 0; nf < 8; nf++) {
                uint32_t bh0 = __float_as_uint(Kh[(nf*8+g)*FPAD + kk+tg]);
                uint32_t bh1 = __float_as_uint(Kh[(nf*8+g)*FPAD + kk+tg+4]);
                uint32_t bl0 = __float_as_uint(Kl[(nf*8+g)*FPAD + kk+tg]);
                uint32_t bl1 = __float_as_uint(Kl[(nf*8+g)*FPAD + kk+tg+4]);
                mma_tf32(s[nf], ah, bh0, bh1);
                mma_tf32(s[nf], ah, bl0, bl1);
                mma_tf32(s[nf], al, bh0, bh1);
            }
        }

        // ---- scale + causal mask ----
        if (kt == qt) {
            int r0l = m0 + g, r1l = r0l + 8;
            #pragma unroll
            for (int nf = 0; nf < 8; nf++) {
                int c0 = nf*8 + 2*tg, c1 = c0 + 1;
                s[nf][0] = (c0 > r0l) ? -FLT_MAX : s[nf][0]*scale;
                s[nf][1] = (c1 > r0l) ? -FLT_MAX : s[nf][1]*scale;
                s[nf][2] = (c0 > r1l) ? -FLT_MAX : s[nf][2]*scale;
                s[nf][3] = (c1 > r1l) ? -FLT_MAX : s[nf][3]*scale;
            }
        } else {
            #pragma unroll
            for (int nf = 0; nf < 8; nf++)
                #pragma unroll
                for (int c = 0; c < 4; c++) s[nf][c] *= scale;
        }

        // ---- online softmax (rows g and g+8; quad shuffles only) ----
        float rm0 = -FLT_MAX, rm1 = -FLT_MAX;
        #pragma unroll
        for (int nf = 0; nf < 8; nf++) {
            rm0 = fmaxf(rm0, fmaxf(s[nf][0], s[nf][1]));
            rm1 = fmaxf(rm1, fmaxf(s[nf][2], s[nf][3]));
        }
        rm0 = fmaxf(rm0, __shfl_xor_sync(0xffffffffu, rm0, 1));
        rm0 = fmaxf(rm0, __shfl_xor_sync(0xffffffffu, rm0, 2));
        rm1 = fmaxf(rm1, __shfl_xor_sync(0xffffffffu, rm1, 1));
        rm1 = fmaxf(rm1, __shfl_xor_sync(0xffffffffu, rm1, 2));
        float mn0 = fmaxf(m_i[0], rm0), mn1 = fmaxf(m_i[1], rm1);
        float fac0 = __expf(m_i[0] - mn0), fac1 = __expf(m_i[1] - mn1);
        m_i[0] = mn0; m_i[1] = mn1;
        float rs0 = 0.f, rs1 = 0.f;
        #pragma unroll
        for (int nf = 0; nf < 8; nf++) {
            s[nf][0] = __expf(s[nf][0] - mn0); rs0 += s[nf][0];
            s[nf][1] = __expf(s[nf][1] - mn0); rs0 += s[nf][1];
            s[nf][2] = __expf(s[nf][2] - mn1); rs1 += s[nf][2];
            s[nf][3] = __expf(s[nf][3] - mn1); rs1 += s[nf][3];
        }
        rs0 += __shfl_xor_sync(0xffffffffu, rs0, 1);
        rs0 += __shfl_xor_sync(0xffffffffu, rs0, 2);
        rs1 += __shfl_xor_sync(0xffffffffu, rs1, 1);
        rs1 += __shfl_xor_sync(0xffffffffu, rs1, 2);
        l_i[0] = l_i[0]*fac0 + rs0;
        l_i[1] = l_i[1]*fac1 + rs1;
        #pragma unroll
        for (int nf = 0; nf < 8; nf++) {
            o[nf][0] *= fac0; o[nf][1] *= fac0;
            o[nf][2] *= fac1; o[nf][3] *= fac1;
        }

        // ---- write P to smem (aliases Kh; all warps must be done with K) ----
        __syncthreads();
        #pragma unroll
        for (int nf = 0; nf < 8; nf++) {
            *(float2*)&Ps[(m0+g)*FPAD   + nf*8 + 2*tg] = make_float2(s[nf][0], s[nf][1]);
            *(float2*)&Ps[(m0+g+8)*FPAD + nf*8 + 2*tg] = make_float2(s[nf][2], s[nf][3]);
        }
        __syncwarp();

        // ---- O += P * V (3xTF32); P rows are warp-private ----
        #pragma unroll 2
        for (int kk = 0; kk < 64; kk += 8) {
            float a0 = Ps[(m0+g)*FPAD   + kk+tg];
            float a1 = Ps[(m0+g+8)*FPAD + kk+tg];
            float a2 = Ps[(m0+g)*FPAD   + kk+tg+4];
            float a3 = Ps[(m0+g+8)*FPAD + kk+tg+4];
            uint32_t ah[4], al[4];
            ah[0] = f2tf32(a0); al[0] = f2tf32(a0 - __uint_as_float(ah[0]));
            ah[1] = f2tf32(a1); al[1] = f2tf32(a1 - __uint_as_float(ah[1]));
            ah[2] = f2tf32(a2); al[2] = f2tf32(a2 - __uint_as_float(ah[2]));
            ah[3] = f2tf32(a3); al[3] = f2tf32(a3 - __uint_as_float(ah[3]));
            #pragma unroll
            for (int nf = 0; nf < 8; nf++) {
                uint32_t bh0 = __float_as_uint(Vh[(kk+tg)*VPAD   + nf*8+g]);
                uint32_t bh1 = __float_as_uint(Vh[(kk+tg+4)*VPAD + nf*8+g]);
                uint32_t bl0 = __float_as_uint(Vl[(kk+tg)*VPAD   + nf*8+g]);
                uint32_t bl1 = __float_as_uint(Vl[(kk+tg+4)*VPAD + nf*8+g]);
                mma_tf32(o[nf], ah, bh0, bh1);
                mma_tf32(o[nf], ah, bl0, bl1);
                mma_tf32(o[nf], al, bh0, bh1);
            }
        }
    }

    // ---- finalize ----
    float inv0 = 1.0f / l_i[0], inv1 = 1.0f / l_i[1];
    size_t r0 = (size_t)b*SEQ + qt*64 + m0 + g;
    float* dst0 = O + r0*QDIM + h*64;
    float* dst1 = dst0 + (size_t)8*QDIM;
    #pragma unroll
    for (int nf = 0; nf < 8; nf++) {
        *(float2*)&dst0[nf*8 + 2*tg] = make_float2(o[nf][0]*inv0, o[nf][1]*inv0);
        *(float2*)&dst1[nf*8 + 2*tg] = make_float2(o[nf][2]*inv1, o[nf][3]*inv1);
    }
}

// ---------------------------------------------------------------------------
extern "C" void kernel_launch(void* const* d_in, const int* in_sizes, int n_in,
                              void* d_out, int out_size) {
    (void)in_sizes; (void)n_in; (void)out_size;
    const float* x  = (const float*)d_in[0];
    const float* wq = (const float*)d_in[1];
    const float* wk = (const float*)d_in[2];
    const float* wv = (const float*)d_in[3];
    const float* wo = (const float*)d_in[4];
    float* out = (float*)d_out;

    float *Qp, *Kp, *Vp, *Ap;
    cudaGetSymbolAddress((void**)&Qp, g_Q);
    cudaGetSymbolAddress((void**)&Kp, g_K);
    cudaGetSymbolAddress((void**)&Vp, g_V);
    cudaGetSymbolAddress((void**)&Ap, g_A);

    static int smem_set = 0;
    if (!smem_set) {
        cudaFuncSetAttribute(flash_tc, cudaFuncAttributeMaxDynamicSharedMemorySize, FLASH_SMEM);
        smem_set = 1;
    }

    rope_table_kernel<<<(SEQ*32 + 255)/256, 256>>>();

    gemm_tf32<<<dim3(QDIM/BN,  TOKENS/BM), 256>>>(x, wq, Qp, TOKENS, QDIM,  DMODEL);
    gemm_tf32<<<dim3(KVDIM/BN, TOKENS/BM), 256>>>(x, wk, Kp, TOKENS, KVDIM, DMODEL);
    gemm_tf32<<<dim3(KVDIM/BN, TOKENS/BM), 256>>>(x, wv, Vp, TOKENS, KVDIM, DMODEL);

    rope_kernel<<<(TOKENS*NH*32 + 255)/256, 256>>>(Qp, NH);
    rope_kernel<<<(TOKENS*NKV*32 + 255)/256, 256>>>(Kp, NKV);

    flash_tc<<<dim3(SEQ/64, BATCH*NH), 128, FLASH_SMEM>>>(Qp, Kp, Vp, Ap);

    gemm_tf32<<<dim3(DMODEL/BN, TOKENS/BM), 256>>>(Ap, wo, out, TOKENS, DMODEL, QDIM);
}

// round 6
// speedup vs baseline: 2.7690x; 1.1889x over previous
#include <cuda_runtime.h>
#include <cuda_bf16.h>
#include <math.h>
#include <float.h>
#include <stdint.h>

// Problem constants
#define BATCH 2
#define SEQ   2048
#define DMODEL 2048
#define NH    32
#define NKV   8
#define REP   4
#define HD    64
#define TOKENS (BATCH*SEQ)   // 4096
#define QDIM  (NH*HD)        // 2048
#define KVDIM (NKV*HD)       // 512

// Scratch (device globals: allocation-free)
__device__ float g_Q[TOKENS*QDIM];
__device__ float g_K[TOKENS*KVDIM];
__device__ float g_V[TOKENS*KVDIM];
__device__ float g_A[TOKENS*QDIM];
__device__ float g_cos[SEQ*(HD/2)];
__device__ float g_sin[SEQ*(HD/2)];

__device__ __forceinline__ uint32_t f2tf32(float x) {
    uint32_t r;
    asm("cvt.rna.tf32.f32 %0, %1;" : "=r"(r) : "f"(x));
    return r;
}
__device__ __forceinline__ float tf32f(float x) {
    return __uint_as_float(f2tf32(x));
}
__device__ __forceinline__ void mma_tf32(float* c, const uint32_t* a, uint32_t b0, uint32_t b1) {
    asm volatile("mma.sync.aligned.m16n8k8.row.col.f32.tf32.tf32.f32 "
                 "{%0,%1,%2,%3}, {%4,%5,%6,%7}, {%8,%9}, {%0,%1,%2,%3};"
                 : "+f"(c[0]), "+f"(c[1]), "+f"(c[2]), "+f"(c[3])
                 : "r"(a[0]), "r"(a[1]), "r"(a[2]), "r"(a[3]), "r"(b0), "r"(b1));
}
__device__ __forceinline__ void cp_async16(void* smem_dst, const void* gmem_src) {
    uint32_t s = (uint32_t)__cvta_generic_to_shared(smem_dst);
    asm volatile("cp.async.cg.shared.global [%0], [%1], 16;" :: "r"(s), "l"(gmem_src));
}
__device__ __forceinline__ void cp_commit() {
    asm volatile("cp.async.commit_group;");
}
template<int N> __device__ __forceinline__ void cp_wait() {
    asm volatile("cp.async.wait_group %0;" :: "n"(N));
}

// ---------------------------------------------------------------------------
// RoPE tables
// ---------------------------------------------------------------------------
__global__ void rope_table_kernel() {
    int idx = blockIdx.x * blockDim.x + threadIdx.x;
    if (idx >= SEQ*(HD/2)) return;
    int pos = idx >> 5;
    int i   = idx & 31;
    double expo = (2.0 * i) / 64.0;
    float invf = (float)(1.0 / pow(10000.0, expo));
    float fr = (float)pos * invf;
    double a = (double)fr;
    g_cos[idx] = (float)cos(a);
    g_sin[idx] = (float)sin(a);
}

// ---------------------------------------------------------------------------
// Pipelined tf32 GEMM body. C[M,N] = A[M,2048]*B[2048,N], row-major.
// Block tile 128x128, BK=16, 3-stage cp.async pipeline, 256 threads,
// 8 warps 4(M)x2(N), warp tile 32x64. Optional fused RoPE epilogue.
// Smem: As[s][128][20] ([m][k], stride 20), Bs[s][16][136] ([k][n]).
// ---------------------------------------------------------------------------
#define GK 2048
#define NSTG 3
#define APITCH 20
#define BPITCH 136
#define ASTG (128*APITCH)
#define BSTG (16*BPITCH)
#define GEMM_SMEM (NSTG*(ASTG+BSTG)*4)   // 56832 B

__device__ __forceinline__ void gemm_body(const float* __restrict__ A,
                                          const float* __restrict__ B,
                                          float* __restrict__ C,
                                          int N, int by, int cb, int rope) {
    extern __shared__ float sm[];
    float* As = sm;                 // [NSTG][128][APITCH]
    float* Bs = sm + NSTG*ASTG;     // [NSTG][16][BPITCH]

    int tid  = threadIdx.x;
    int lane = tid & 31, warp = tid >> 5;
    int wm = warp & 3, wn = warp >> 2;
    int m_warp = wm * 32, n_warp = wn * 64;
    int g  = lane >> 2;
    int tg = lane & 3;

    const float* Ablk = A + (size_t)by * 128 * GK;
    const float* Bblk = B + (size_t)cb * 128;

    // cp.async assignments (2 float4 per thread per matrix per stage)
    int a_r0 = tid >> 1, a_k0 = (tid & 1) * 8;          // A: rows 0..127, 2x float4
    int b_r0 = tid >> 4, b_n0 = (tid & 15) * 8;         // B: k-rows 0..15, 2x float4

    float acc[2][8][4];
    #pragma unroll
    for (int mi = 0; mi < 2; mi++)
        #pragma unroll
        for (int ni = 0; ni < 8; ni++)
            #pragma unroll
            for (int c = 0; c < 4; c++) acc[mi][ni][c] = 0.f;

    // prologue: stages 0..NSTG-2
    #pragma unroll
    for (int s = 0; s < NSTG-1; s++) {
        int k0 = s * 16;
        float* as = As + s*ASTG;
        float* bs = Bs + s*BSTG;
        cp_async16(&as[a_r0*APITCH + a_k0],     &Ablk[(size_t)a_r0*GK + k0 + a_k0]);
        cp_async16(&as[a_r0*APITCH + a_k0 + 4], &Ablk[(size_t)a_r0*GK + k0 + a_k0 + 4]);
        cp_async16(&bs[b_r0*BPITCH + b_n0],     &Bblk[(size_t)(k0+b_r0)*N + b_n0]);
        cp_async16(&bs[b_r0*BPITCH + b_n0 + 4], &Bblk[(size_t)(k0+b_r0)*N + b_n0 + 4]);
        cp_commit();
    }

    const int NITER = GK / 16;
    int s = 0;
    for (int it = 0; it < NITER; it++) {
        cp_wait<NSTG-2>();
        __syncthreads();

        // issue stage it+NSTG-1 (overwrites buffer (it-1)%NSTG, consumed last iter)
        int kpre = (it + NSTG - 1) * 16;
        if (kpre < GK) {
            int sp = (it + NSTG - 1) % NSTG;
            float* as = As + sp*ASTG;
            float* bs = Bs + sp*BSTG;
            cp_async16(&as[a_r0*APITCH + a_k0],     &Ablk[(size_t)a_r0*GK + kpre + a_k0]);
            cp_async16(&as[a_r0*APITCH + a_k0 + 4], &Ablk[(size_t)a_r0*GK + kpre + a_k0 + 4]);
            cp_async16(&bs[b_r0*BPITCH + b_n0],     &Bblk[(size_t)(kpre+b_r0)*N + b_n0]);
            cp_async16(&bs[b_r0*BPITCH + b_n0 + 4], &Bblk[(size_t)(kpre+b_r0)*N + b_n0 + 4]);
        }
        cp_commit();

        const float* as = As + s*ASTG;
        const float* bs = Bs + s*BSTG;
        #pragma unroll
        for (int kk = 0; kk < 16; kk += 8) {
            uint32_t afr[2][4];
            #pragma unroll
            for (int mi = 0; mi < 2; mi++) {
                int mb = m_warp + mi*16;
                afr[mi][0] = f2tf32(as[(mb+g)*APITCH   + kk+tg]);
                afr[mi][1] = f2tf32(as[(mb+g+8)*APITCH + kk+tg]);
                afr[mi][2] = f2tf32(as[(mb+g)*APITCH   + kk+tg+4]);
                afr[mi][3] = f2tf32(as[(mb+g+8)*APITCH + kk+tg+4]);
            }
            uint32_t bfr[8][2];
            #pragma unroll
            for (int ni = 0; ni < 8; ni++) {
                int nb = n_warp + ni*8;
                bfr[ni][0] = f2tf32(bs[(kk+tg)*BPITCH   + nb + g]);
                bfr[ni][1] = f2tf32(bs[(kk+tg+4)*BPITCH + nb + g]);
            }
            #pragma unroll
            for (int mi = 0; mi < 2; mi++)
                #pragma unroll
                for (int ni = 0; ni < 8; ni++)
                    mma_tf32(acc[mi][ni], afr[mi], bfr[ni][0], bfr[ni][1]);
        }
        s = (s + 1) % NSTG;
    }

    // ---- epilogue (optional fused RoPE: warp tile = exactly one head) ----
    if (rope) {
        #pragma unroll
        for (int mi = 0; mi < 2; mi++) {
            int ra = by*128 + m_warp + mi*16 + g;   // rows for comps 0,1
            int pa = ra & (SEQ-1);
            int pb = (ra + 8) & (SEQ-1);
            #pragma unroll
            for (int ni = 0; ni < 4; ni++) {
                int i0 = ni*8 + tg*2;
                float ca0 = g_cos[pa*32 + i0], sa0 = g_sin[pa*32 + i0];
                float ca1 = g_cos[pa*32 + i0+1], sa1 = g_sin[pa*32 + i0+1];
                float cb0 = g_cos[pb*32 + i0], sb0 = g_sin[pb*32 + i0];
                float cb1 = g_cos[pb*32 + i0+1], sb1 = g_sin[pb*32 + i0+1];
                float x1, x2;
                x1 = acc[mi][ni][0]; x2 = acc[mi][ni+4][0];
                acc[mi][ni][0] = x1*ca0 - x2*sa0; acc[mi][ni+4][0] = x1*sa0 + x2*ca0;
                x1 = acc[mi][ni][1]; x2 = acc[mi][ni+4][1];
                acc[mi][ni][1] = x1*ca1 - x2*sa1; acc[mi][ni+4][1] = x1*sa1 + x2*ca1;
                x1 = acc[mi][ni][2]; x2 = acc[mi][ni+4][2];
                acc[mi][ni][2] = x1*cb0 - x2*sb0; acc[mi][ni+4][2] = x1*sb0 + x2*cb0;
                x1 = acc[mi][ni][3]; x2 = acc[mi][ni+4][3];
                acc[mi][ni][3] = x1*cb1 - x2*sb1; acc[mi][ni+4][3] = x1*sb1 + x2*cb1;
            }
        }
    }

    size_t rowbase = (size_t)by * 128 + m_warp + g;
    int colbase = cb * 128 + n_warp + tg*2;
    #pragma unroll
    for (int mi = 0; mi < 2; mi++) {
        size_t r0 = rowbase + mi*16;
        #pragma unroll
        for (int ni = 0; ni < 8; ni++) {
            int c = colbase + ni*8;
            *(float2*)&C[r0*N + c]     = make_float2(acc[mi][ni][0], acc[mi][ni][1]);
            *(float2*)&C[(r0+8)*N + c] = make_float2(acc[mi][ni][2], acc[mi][ni][3]);
        }
    }
}

// Fused QKV projection + RoPE. grid = (24, 32): bx 0..15 -> Q, 16..19 -> K, 20..23 -> V
__global__ __launch_bounds__(256) void qkv_kernel(const float* __restrict__ x,
                                                  const float* __restrict__ wq,
                                                  const float* __restrict__ wk,
                                                  const float* __restrict__ wv) {
    int bx = blockIdx.x;
    const float* B; float* C; int N, cb, rope;
    if (bx < 16)      { B = wq; C = g_Q; N = QDIM;  cb = bx;      rope = 1; }
    else if (bx < 20) { B = wk; C = g_K; N = KVDIM; cb = bx - 16; rope = 1; }
    else              { B = wv; C = g_V; N = KVDIM; cb = bx - 20; rope = 0; }
    gemm_body(x, B, C, N, blockIdx.y, cb, rope);
}

// Output projection. grid = (16, 32)
__global__ __launch_bounds__(256) void outproj_kernel(const float* __restrict__ wo,
                                                      float* __restrict__ out) {
    gemm_body(g_A, wo, out, DMODEL, blockIdx.y, blockIdx.x, 0);
}

// ---------------------------------------------------------------------------
// Tensor-core causal flash attention, 3xTF32 (unchanged from R5).
// ---------------------------------------------------------------------------
#define FPAD 68
#define VPAD 72
#define FLASH_SMEM ((3*64*FPAD + 2*64*VPAD)*4)   // 89088 bytes

__global__ __launch_bounds__(128) void flash_tc(const float* __restrict__ Q,
                                                const float* __restrict__ K,
                                                const float* __restrict__ V,
                                                float* __restrict__ O) {
    extern __shared__ float sm[];
    float* Qs = sm;
    float* Kh = Qs + 64*FPAD;
    float* Kl = Kh + 64*FPAD;
    float* Vh = Kl + 64*FPAD;
    float* Vl = Vh + 64*VPAD;
    float* Ps = Kh;

    int qt = blockIdx.x;
    int bh = blockIdx.y;
    int b = bh >> 5, h = bh & 31, gkv = h >> 2;
    int tid = threadIdx.x;
    int lane = tid & 31, warp = tid >> 5;
    int g = lane >> 2, tg = lane & 3;
    int m0 = warp * 16;

    const float* Qbase = Q + (size_t)b*SEQ*QDIM + (size_t)(qt*64)*QDIM + h*64;
    const float* Kbase = K + (size_t)b*SEQ*KVDIM + gkv*64;
    const float* Vbase = V + (size_t)b*SEQ*KVDIM + gkv*64;

    {
        int r = tid >> 1, c0 = (tid & 1) * 32;
        const float* src = Qbase + (size_t)r*QDIM + c0;
        float* dst = Qs + r*FPAD + c0;
        #pragma unroll
        for (int i = 0; i < 8; i++)
            *(float4*)(dst + i*4) = *(const float4*)(src + i*4);
    }

    float m_i[2] = {-FLT_MAX, -FLT_MAX};
    float l_i[2] = {0.f, 0.f};
    float o[8][4];
    #pragma unroll
    for (int nf = 0; nf < 8; nf++)
        #pragma unroll
        for (int c = 0; c < 4; c++) o[nf][c] = 0.f;

    const float scale = 0.125f;

    for (int kt = 0; kt <= qt; kt++) {
        __syncthreads();
        {
            int r = tid >> 1, c0 = (tid & 1) * 32;
            const float* ksrc = Kbase + (size_t)(kt*64 + r)*KVDIM + c0;
            const float* vsrc = Vbase + (size_t)(kt*64 + r)*KVDIM + c0;
            float* khd = Kh + r*FPAD + c0;
            float* kld = Kl + r*FPAD + c0;
            float* vhd = Vh + r*VPAD + c0;
            float* vld = Vl + r*VPAD + c0;
            #pragma unroll
            for (int i = 0; i < 8; i++) {
                float4 kv = *(const float4*)(ksrc + i*4);
                float4 vv = *(const float4*)(vsrc + i*4);
                float4 kh4, kl4, vh4, vl4;
                kh4.x = tf32f(kv.x); kl4.x = tf32f(kv.x - kh4.x);
                kh4.y = tf32f(kv.y); kl4.y = tf32f(kv.y - kh4.y);
                kh4.z = tf32f(kv.z); kl4.z = tf32f(kv.z - kh4.z);
                kh4.w = tf32f(kv.w); kl4.w = tf32f(kv.w - kh4.w);
                vh4.x = tf32f(vv.x); vl4.x = tf32f(vv.x - vh4.x);
                vh4.y = tf32f(vv.y); vl4.y = tf32f(vv.y - vh4.y);
                vh4.z = tf32f(vv.z); vl4.z = tf32f(vv.z - vh4.z);
                vh4.w = tf32f(vv.w); vl4.w = tf32f(vv.w - vh4.w);
                *(float4*)(khd + i*4) = kh4;
                *(float4*)(kld + i*4) = kl4;
                *(float4*)(vhd + i*4) = vh4;
                *(float4*)(vld + i*4) = vl4;
            }
        }
        __syncthreads();

        float s[8][4];
        #pragma unroll
        for (int nf = 0; nf < 8; nf++)
            #pragma unroll
            for (int c = 0; c < 4; c++) s[nf][c] = 0.f;

        #pragma unroll 2
        for (int kk = 0; kk < 64; kk += 8) {
            float a0 = Qs[(m0+g)*FPAD   + kk+tg];
            float a1 = Qs[(m0+g+8)*FPAD + kk+tg];
            float a2 = Qs[(m0+g)*FPAD   + kk+tg+4];
            float a3 = Qs[(m0+g+8)*FPAD + kk+tg+4];
            uint32_t ah[4], al[4];
            ah[0] = f2tf32(a0); al[0] = f2tf32(a0 - __uint_as_float(ah[0]));
            ah[1] = f2tf32(a1); al[1] = f2tf32(a1 - __uint_as_float(ah[1]));
            ah[2] = f2tf32(a2); al[2] = f2tf32(a2 - __uint_as_float(ah[2]));
            ah[3] = f2tf32(a3); al[3] = f2tf32(a3 - __uint_as_float(ah[3]));
            #pragma unroll
            for (int nf = 0; nf < 8; nf++) {
                uint32_t bh0 = __float_as_uint(Kh[(nf*8+g)*FPAD + kk+tg]);
                uint32_t bh1 = __float_as_uint(Kh[(nf*8+g)*FPAD + kk+tg+4]);
                uint32_t bl0 = __float_as_uint(Kl[(nf*8+g)*FPAD + kk+tg]);
                uint32_t bl1 = __float_as_uint(Kl[(nf*8+g)*FPAD + kk+tg+4]);
                mma_tf32(s[nf], ah, bh0, bh1);
                mma_tf32(s[nf], ah, bl0, bl1);
                mma_tf32(s[nf], al, bh0, bh1);
            }
        }

        if (kt == qt) {
            int r0l = m0 + g, r1l = r0l + 8;
            #pragma unroll
            for (int nf = 0; nf < 8; nf++) {
                int c0 = nf*8 + 2*tg, c1 = c0 + 1;
                s[nf][0] = (c0 > r0l) ? -FLT_MAX : s[nf][0]*scale;
                s[nf][1] = (c1 > r0l) ? -FLT_MAX : s[nf][1]*scale;
                s[nf][2] = (c0 > r1l) ? -FLT_MAX : s[nf][2]*scale;
                s[nf][3] = (c1 > r1l) ? -FLT_MAX : s[nf][3]*scale;
            }
        } else {
            #pragma unroll
            for (int nf = 0; nf < 8; nf++)
                #pragma unroll
                for (int c = 0; c < 4; c++) s[nf][c] *= scale;
        }

        float rm0 = -FLT_MAX, rm1 = -FLT_MAX;
        #pragma unroll
        for (int nf = 0; nf < 8; nf++) {
            rm0 = fmaxf(rm0, fmaxf(s[nf][0], s[nf][1]));
            rm1 = fmaxf(rm1, fmaxf(s[nf][2], s[nf][3]));
        }
        rm0 = fmaxf(rm0, __shfl_xor_sync(0xffffffffu, rm0, 1));
        rm0 = fmaxf(rm0, __shfl_xor_sync(0xffffffffu, rm0, 2));
        rm1 = fmaxf(rm1, __shfl_xor_sync(0xffffffffu, rm1, 1));
        rm1 = fmaxf(rm1, __shfl_xor_sync(0xffffffffu, rm1, 2));
        float mn0 = fmaxf(m_i[0], rm0), mn1 = fmaxf(m_i[1], rm1);
        float fac0 = __expf(m_i[0] - mn0), fac1 = __expf(m_i[1] - mn1);
        m_i[0] = mn0; m_i[1] = mn1;
        float rs0 = 0.f, rs1 = 0.f;
        #pragma unroll
        for (int nf = 0; nf < 8; nf++) {
            s[nf][0] = __expf(s[nf][0] - mn0); rs0 += s[nf][0];
            s[nf][1] = __expf(s[nf][1] - mn0); rs0 += s[nf][1];
            s[nf][2] = __expf(s[nf][2] - mn1); rs1 += s[nf][2];
            s[nf][3] = __expf(s[nf][3] - mn1); rs1 += s[nf][3];
        }
        rs0 += __shfl_xor_sync(0xffffffffu, rs0, 1);
        rs0 += __shfl_xor_sync(0xffffffffu, rs0, 2);
        rs1 += __shfl_xor_sync(0xffffffffu, rs1, 1);
        rs1 += __shfl_xor_sync(0xffffffffu, rs1, 2);
        l_i[0] = l_i[0]*fac0 + rs0;
        l_i[1] = l_i[1]*fac1 + rs1;
        #pragma unroll
        for (int nf = 0; nf < 8; nf++) {
            o[nf][0] *= fac0; o[nf][1] *= fac0;
            o[nf][2] *= fac1; o[nf][3] *= fac1;
        }

        __syncthreads();
        #pragma unroll
        for (int nf = 0; nf < 8; nf++) {
            *(float2*)&Ps[(m0+g)*FPAD   + nf*8 + 2*tg] = make_float2(s[nf][0], s[nf][1]);
            *(float2*)&Ps[(m0+g+8)*FPAD + nf*8 + 2*tg] = make_float2(s[nf][2], s[nf][3]);
        }
        __syncwarp();

        #pragma unroll 2
        for (int kk = 0; kk < 64; kk += 8) {
            float a0 = Ps[(m0+g)*FPAD   + kk+tg];
            float a1 = Ps[(m0+g+8)*FPAD + kk+tg];
            float a2 = Ps[(m0+g)*FPAD   + kk+tg+4];
            float a3 = Ps[(m0+g+8)*FPAD + kk+tg+4];
            uint32_t ah[4], al[4];
            ah[0] = f2tf32(a0); al[0] = f2tf32(a0 - __uint_as_float(ah[0]));
            ah[1] = f2tf32(a1); al[1] = f2tf32(a1 - __uint_as_float(ah[1]));
            ah[2] = f2tf32(a2); al[2] = f2tf32(a2 - __uint_as_float(ah[2]));
            ah[3] = f2tf32(a3); al[3] = f2tf32(a3 - __uint_as_float(ah[3]));
            #pragma unroll
            for (int nf = 0; nf < 8; nf++) {
                uint32_t bh0 = __float_as_uint(Vh[(kk+tg)*VPAD   + nf*8+g]);
                uint32_t bh1 = __float_as_uint(Vh[(kk+tg+4)*VPAD + nf*8+g]);
                uint32_t bl0 = __float_as_uint(Vl[(kk+tg)*VPAD   + nf*8+g]);
                uint32_t bl1 = __float_as_uint(Vl[(kk+tg+4)*VPAD + nf*8+g]);
                mma_tf32(o[nf], ah, bh0, bh1);
                mma_tf32(o[nf], ah, bl0, bl1);
                mma_tf32(o[nf], al, bh0, bh1);
            }
        }
    }

    float inv0 = 1.0f / l_i[0], inv1 = 1.0f / l_i[1];
    size_t r0 = (size_t)b*SEQ + qt*64 + m0 + g;
    float* dst0 = O + r0*QDIM + h*64;
    float* dst1 = dst0 + (size_t)8*QDIM;
    #pragma unroll
    for (int nf = 0; nf < 8; nf++) {
        *(float2*)&dst0[nf*8 + 2*tg] = make_float2(o[nf][0]*inv0, o[nf][1]*inv0);
        *(float2*)&dst1[nf*8 + 2*tg] = make_float2(o[nf][2]*inv1, o[nf][3]*inv1);
    }
}

// ---------------------------------------------------------------------------
extern "C" void kernel_launch(void* const* d_in, const int* in_sizes, int n_in,
                              void* d_out, int out_size) {
    (void)in_sizes; (void)n_in; (void)out_size;
    const float* x  = (const float*)d_in[0];
    const float* wq = (const float*)d_in[1];
    const float* wk = (const float*)d_in[2];
    const float* wv = (const float*)d_in[3];
    const float* wo = (const float*)d_in[4];
    float* out = (float*)d_out;

    float *Qp, *Kp, *Vp, *Ap;
    cudaGetSymbolAddress((void**)&Qp, g_Q);
    cudaGetSymbolAddress((void**)&Kp, g_K);
    cudaGetSymbolAddress((void**)&Vp, g_V);
    cudaGetSymbolAddress((void**)&Ap, g_A);

    static int attr_set = 0;
    if (!attr_set) {
        cudaFuncSetAttribute(flash_tc, cudaFuncAttributeMaxDynamicSharedMemorySize, FLASH_SMEM);
        cudaFuncSetAttribute(qkv_kernel, cudaFuncAttributeMaxDynamicSharedMemorySize, GEMM_SMEM);
        cudaFuncSetAttribute(outproj_kernel, cudaFuncAttributeMaxDynamicSharedMemorySize, GEMM_SMEM);
        attr_set = 1;
    }

    rope_table_kernel<<<(SEQ*32 + 255)/256, 256>>>();

    qkv_kernel<<<dim3(24, TOKENS/128), 256, GEMM_SMEM>>>(x, wq, wk, wv);

    flash_tc<<<dim3(SEQ/64, BATCH*NH), 128, FLASH_SMEM>>>(Qp, Kp, Vp, Ap);

    outproj_kernel<<<dim3(DMODEL/128, TOKENS/128), 256, GEMM_SMEM>>>(wo, out);
}